// round 1
// baseline (speedup 1.0000x reference)
#include <cuda_runtime.h>
#include <math.h>

// Problem dims
#define B_ 512
#define S_ 128
#define D_ 256
#define H_ 4
#define DH_ 64
#define FF_ 384
#define L_ 6
#define ROWS_ (B_ * S_)          // 65536
#define SCALE_ 0.125f            // DH^-0.5

// ---------------- scratch (device globals; no runtime allocation) ----------
__device__ float g_h  [(size_t)ROWS_ * D_];        // 64 MB
__device__ float g_hn [(size_t)ROWS_ * D_];        // 64 MB
__device__ float g_qkv[(size_t)ROWS_ * 3 * D_];    // 192 MB
__device__ float g_tmp[(size_t)ROWS_ * FF_];       // 96 MB (attn-out / ffn mid)

// ---------------- embedding + positional encoding ---------------------------
__global__ __launch_bounds__(256) void embed_kernel(
    const int* __restrict__ x, const float* __restrict__ ew,
    float* __restrict__ h)
{
    int row = blockIdx.x;            // 0..65535  (b*128 + s)
    int d   = threadIdx.x;           // 0..255
    int s   = row & (S_ - 1);
    int tok = x[row];
    int p   = d >> 1;
    float dim_t = powf(10000.0f, (float)p * (1.0f / 128.0f));
    float pos   = (float)s / dim_t;
    float pe    = (d & 1) ? cosf(pos) : sinf(pos);
    h[(size_t)row * D_ + d] = ew[(size_t)tok * D_ + d] + pe;
}

// ---------------- LayerNorm: one warp per 256-elem row ----------------------
__global__ __launch_bounds__(256) void ln_kernel(
    const float* __restrict__ in, float* __restrict__ out,
    const float* __restrict__ w, const float* __restrict__ b)
{
    int warp = threadIdx.x >> 5, lane = threadIdx.x & 31;
    size_t row = (size_t)blockIdx.x * 8 + warp;
    const float* p = in + row * D_;
    float4 a0 = *(const float4*)(p + lane * 4);
    float4 a1 = *(const float4*)(p + 128 + lane * 4);
    float s = a0.x + a0.y + a0.z + a0.w + a1.x + a1.y + a1.z + a1.w;
    float q = a0.x*a0.x + a0.y*a0.y + a0.z*a0.z + a0.w*a0.w
            + a1.x*a1.x + a1.y*a1.y + a1.z*a1.z + a1.w*a1.w;
#pragma unroll
    for (int o = 16; o > 0; o >>= 1) {
        s += __shfl_xor_sync(0xffffffffu, s, o);
        q += __shfl_xor_sync(0xffffffffu, q, o);
    }
    float mean = s * (1.0f / 256.0f);
    float var  = q * (1.0f / 256.0f) - mean * mean;
    float rstd = rsqrtf(var + 1e-5f);
    float4 w0 = *(const float4*)(w + lane * 4);
    float4 w1 = *(const float4*)(w + 128 + lane * 4);
    float4 b0 = *(const float4*)(b + lane * 4);
    float4 b1 = *(const float4*)(b + 128 + lane * 4);
    float4 o0, o1;
    o0.x = (a0.x - mean) * rstd * w0.x + b0.x;
    o0.y = (a0.y - mean) * rstd * w0.y + b0.y;
    o0.z = (a0.z - mean) * rstd * w0.z + b0.z;
    o0.w = (a0.w - mean) * rstd * w0.w + b0.w;
    o1.x = (a1.x - mean) * rstd * w1.x + b1.x;
    o1.y = (a1.y - mean) * rstd * w1.y + b1.y;
    o1.z = (a1.z - mean) * rstd * w1.z + b1.z;
    o1.w = (a1.w - mean) * rstd * w1.w + b1.w;
    float* po = out + row * D_;
    *(float4*)(po + lane * 4)       = o0;
    *(float4*)(po + 128 + lane * 4) = o1;
}

// ---------------- SGEMM: C[M,N] = A[M,K] @ W[N,K]^T (+bias)(+gelu)(+res) ----
// 128x128 tile, BK=8, 256 threads, 8x8 per thread.
template<bool GELU, bool RES>
__global__ __launch_bounds__(256) void gemm_kernel(
    const float* __restrict__ A, const float* __restrict__ W,
    const float* __restrict__ bias, const float* __restrict__ res,
    float* __restrict__ C, int M, int N, int K)
{
    __shared__ float As[8][132];
    __shared__ float Bs[8][132];
    const int tid = threadIdx.x;
    const int tx = tid & 15;
    const int ty = tid >> 4;
    const int bm = blockIdx.y << 7;
    const int bn = blockIdx.x << 7;
    const int lr = tid >> 1;             // 0..127 tile row
    const int lk = (tid & 1) << 2;       // 0 or 4
    const float* Ap = A + (size_t)(bm + lr) * K + lk;
    const float* Wp = W + (size_t)(bn + lr) * K + lk;

    float acc[8][8];
#pragma unroll
    for (int i = 0; i < 8; i++)
#pragma unroll
        for (int j = 0; j < 8; j++) acc[i][j] = 0.0f;

    for (int k0 = 0; k0 < K; k0 += 8) {
        float4 av = *(const float4*)(Ap + k0);
        float4 wv = *(const float4*)(Wp + k0);
        __syncthreads();
        As[lk + 0][lr] = av.x; As[lk + 1][lr] = av.y;
        As[lk + 2][lr] = av.z; As[lk + 3][lr] = av.w;
        Bs[lk + 0][lr] = wv.x; Bs[lk + 1][lr] = wv.y;
        Bs[lk + 2][lr] = wv.z; Bs[lk + 3][lr] = wv.w;
        __syncthreads();
#pragma unroll
        for (int kk = 0; kk < 8; kk++) {
            float a[8], bf[8];
            *(float4*)(a)      = *(const float4*)(&As[kk][ty * 4]);
            *(float4*)(a + 4)  = *(const float4*)(&As[kk][ty * 4 + 64]);
            *(float4*)(bf)     = *(const float4*)(&Bs[kk][tx * 4]);
            *(float4*)(bf + 4) = *(const float4*)(&Bs[kk][tx * 4 + 64]);
#pragma unroll
            for (int i = 0; i < 8; i++)
#pragma unroll
                for (int j = 0; j < 8; j++)
                    acc[i][j] = fmaf(a[i], bf[j], acc[i][j]);
        }
    }

#pragma unroll
    for (int i = 0; i < 8; i++) {
        int r = bm + ty * 4 + (i & 3) + (i >> 2) * 64;
#pragma unroll
        for (int j = 0; j < 8; j++) {
            int c = bn + tx * 4 + (j & 3) + (j >> 2) * 64;
            float v = acc[i][j];
            if (bias) v += bias[c];
            if (GELU) v = 0.5f * v * (1.0f + erff(v * 0.70710678118654752f));
            if (RES)  v += res[(size_t)r * N + c];
            C[(size_t)r * N + c] = v;
        }
    }
}

// ---------------- attention: one block per (head, batch) --------------------
// 128 threads, each owns one query row. K,V,scores in SMEM; q/o in registers.
#define ATTN_SMEM ((2 * 128 * 64 + 128 * 129) * 4)   // 131584 bytes

__global__ __launch_bounds__(128) void attn_kernel(
    const float* __restrict__ qkv, const float* __restrict__ ids,
    float* __restrict__ out)
{
    extern __shared__ float sm[];
    float* Ks = sm;                  // [128][64]
    float* Vs = sm + 128 * 64;       // [128][64]
    float* Sc = sm + 2 * 128 * 64;   // [128][129]
    int h = blockIdx.x, b = blockIdx.y, t = threadIdx.x;
    const float* base = qkv + (size_t)b * S_ * (3 * D_);
    const int qoff = h * DH_;
    const int koff = D_ + h * DH_;
    const int voff = 2 * D_ + h * DH_;

    for (int idx = t; idx < 128 * 16; idx += 128) {
        int r = idx >> 4, c = (idx & 15) << 2;
        *(float4*)(Ks + r * 64 + c) = *(const float4*)(base + (size_t)r * 768 + koff + c);
        *(float4*)(Vs + r * 64 + c) = *(const float4*)(base + (size_t)r * 768 + voff + c);
    }
    float q[64];
    {
        const float* qp = base + (size_t)t * 768 + qoff;
#pragma unroll
        for (int i = 0; i < 16; i++) {
            float4 v = *(const float4*)(qp + i * 4);
            q[i*4] = v.x; q[i*4+1] = v.y; q[i*4+2] = v.z; q[i*4+3] = v.w;
        }
    }
    __syncthreads();

    float mx = -1e30f;
    float* srow = Sc + t * 129;
    const float* idrow = ids + b * S_;
    for (int j = 0; j < 128; j++) {
        float dot = 0.0f;
        const float* kr = Ks + j * 64;
#pragma unroll
        for (int i = 0; i < 16; i++) {
            float4 kv = *(const float4*)(kr + i * 4);
            dot = fmaf(q[i*4], kv.x, dot);
            dot = fmaf(q[i*4+1], kv.y, dot);
            dot = fmaf(q[i*4+2], kv.z, dot);
            dot = fmaf(q[i*4+3], kv.w, dot);
        }
        float sc = (dot + idrow[j] * -1e9f) * SCALE_;
        srow[j] = sc;
        mx = fmaxf(mx, sc);
    }
    float sum = 0.0f;
    for (int j = 0; j < 128; j++) {
        float e = expf(srow[j] - mx);
        srow[j] = e;
        sum += e;
    }
    float inv = 1.0f / sum;

    float o[64];
#pragma unroll
    for (int i = 0; i < 64; i++) o[i] = 0.0f;
    for (int j = 0; j < 128; j++) {
        float p = srow[j];
        const float* vr = Vs + j * 64;
#pragma unroll
        for (int i = 0; i < 16; i++) {
            float4 vv = *(const float4*)(vr + i * 4);
            o[i*4]   = fmaf(p, vv.x, o[i*4]);
            o[i*4+1] = fmaf(p, vv.y, o[i*4+1]);
            o[i*4+2] = fmaf(p, vv.z, o[i*4+2]);
            o[i*4+3] = fmaf(p, vv.w, o[i*4+3]);
        }
    }
    float* op = out + (size_t)(b * S_ + t) * D_ + h * DH_;
#pragma unroll
    for (int i = 0; i < 16; i++) {
        float4 v = make_float4(o[i*4] * inv, o[i*4+1] * inv,
                               o[i*4+2] * inv, o[i*4+3] * inv);
        *(float4*)(op + i * 4) = v;
    }
}

// ---------------- final logits: out[b,c] = flat[b,:] . W[c,:] + bias --------
__global__ __launch_bounds__(256) void logits_kernel(
    const float* __restrict__ hflat, const float* __restrict__ W,
    const float* __restrict__ bias, float* __restrict__ out)
{
    int b = blockIdx.x, t = threadIdx.x;
    const float4* h4  = (const float4*)(hflat + (size_t)b * 32768);
    const float4* w04 = (const float4*)(W);
    const float4* w14 = (const float4*)(W + 32768);
    float a0 = 0.0f, a1 = 0.0f;
    for (int i = t; i < 8192; i += 256) {
        float4 x = h4[i], u = w04[i], v = w14[i];
        a0 += x.x*u.x + x.y*u.y + x.z*u.z + x.w*u.w;
        a1 += x.x*v.x + x.y*v.y + x.z*v.z + x.w*v.w;
    }
    __shared__ float r0[256], r1[256];
    r0[t] = a0; r1[t] = a1;
    __syncthreads();
    for (int s = 128; s > 0; s >>= 1) {
        if (t < s) { r0[t] += r0[t + s]; r1[t] += r1[t + s]; }
        __syncthreads();
    }
    if (t == 0) {
        out[b * 2 + 0] = r0[0] + bias[0];
        out[b * 2 + 1] = r1[0] + bias[1];
    }
}

// ---------------- launch --------------------------------------------------
extern "C" void kernel_launch(void* const* d_in, const int* in_sizes, int n_in,
                              void* d_out, int out_size)
{
    const int*   x    = (const int*)  d_in[0];
    const float* ids  = (const float*)d_in[1];
    const float* ew   = (const float*)d_in[2];
    const float* n1w  = (const float*)d_in[3];
    const float* n1b  = (const float*)d_in[4];
    const float* piw  = (const float*)d_in[5];
    const float* pow_ = (const float*)d_in[6];
    const float* pob  = (const float*)d_in[7];
    const float* n2w  = (const float*)d_in[8];
    const float* n2b  = (const float*)d_in[9];
    const float* l1w  = (const float*)d_in[10];
    const float* l1b  = (const float*)d_in[11];
    const float* l2w  = (const float*)d_in[12];
    const float* l2b  = (const float*)d_in[13];
    const float* lw   = (const float*)d_in[14];
    const float* lb   = (const float*)d_in[15];
    float* out = (float*)d_out;

    float *h, *hn, *qkvb, *tmp;
    cudaGetSymbolAddress((void**)&h,    g_h);
    cudaGetSymbolAddress((void**)&hn,   g_hn);
    cudaGetSymbolAddress((void**)&qkvb, g_qkv);
    cudaGetSymbolAddress((void**)&tmp,  g_tmp);

    cudaFuncSetAttribute(attn_kernel,
                         cudaFuncAttributeMaxDynamicSharedMemorySize, ATTN_SMEM);

    embed_kernel<<<ROWS_, 256>>>(x, ew, h);

    for (int l = 0; l < L_; l++) {
        // hn = LN(h)
        ln_kernel<<<ROWS_ / 8, 256>>>(h, hn, n1w + l * D_, n1b + l * D_);
        // qkv = hn @ Wqkv^T
        gemm_kernel<false, false><<<dim3(6, 512), 256>>>(
            hn, piw + (size_t)l * 3 * D_ * D_, nullptr, nullptr,
            qkvb, ROWS_, 3 * D_, D_);
        // attention -> tmp [ROWS, D]
        attn_kernel<<<dim3(H_, B_), 128, ATTN_SMEM>>>(qkvb, ids, tmp);
        // h = tmp @ Wo^T + bo + hn
        gemm_kernel<false, true><<<dim3(2, 512), 256>>>(
            tmp, pow_ + (size_t)l * D_ * D_, pob + l * D_, hn,
            h, ROWS_, D_, D_);
        // hn = LN(h)
        ln_kernel<<<ROWS_ / 8, 256>>>(h, hn, n2w + l * D_, n2b + l * D_);
        // tmp = gelu(hn @ W1^T + b1)   [ROWS, FF]
        gemm_kernel<true, false><<<dim3(3, 512), 256>>>(
            hn, l1w + (size_t)l * FF_ * D_, l1b + l * FF_, nullptr,
            tmp, ROWS_, FF_, D_);
        // h = tmp @ W2^T + b2 + hn
        gemm_kernel<false, true><<<dim3(2, 512), 256>>>(
            tmp, l2w + (size_t)l * D_ * FF_, l2b + l * D_, hn,
            h, ROWS_, D_, FF_);
    }

    logits_kernel<<<B_, 256>>>(h, lw, lb, out);
}

// round 4
// speedup vs baseline: 1.7473x; 1.7473x over previous
#include <cuda_runtime.h>
#include <cuda_bf16.h>
#include <cstdint>
#include <math.h>

// Problem dims
#define B_ 512
#define S_ 128
#define D_ 256
#define H_ 4
#define DH_ 64
#define FF_ 384
#define L_ 6
#define ROWS_ (B_ * S_)          // 65536
#define SCALE_ 0.125f            // DH^-0.5

// ---------------- scratch (device globals; no runtime allocation) ----------
__device__ float g_h  [(size_t)ROWS_ * D_];
__device__ float g_hn [(size_t)ROWS_ * D_];
__device__ float g_qkv[(size_t)ROWS_ * 3 * D_];
__device__ float g_tmp[(size_t)ROWS_ * FF_];

extern __shared__ char dyn_smem[];

// ======================= helpers ===========================================
__device__ __forceinline__ uint32_t smem_u32(const void* p) {
    uint32_t a;
    asm("{ .reg .u64 t; cvta.to.shared.u64 t, %1; cvt.u32.u64 %0, t; }"
        : "=r"(a) : "l"(p));
    return a;
}

__device__ __forceinline__ void ldsm4(uint32_t a, uint32_t* r) {
    asm volatile("ldmatrix.sync.aligned.m8n8.x4.shared.b16 {%0,%1,%2,%3}, [%4];"
                 : "=r"(r[0]), "=r"(r[1]), "=r"(r[2]), "=r"(r[3]) : "r"(a));
}
__device__ __forceinline__ void ldsm2(uint32_t a, uint32_t* r) {
    asm volatile("ldmatrix.sync.aligned.m8n8.x2.shared.b16 {%0,%1}, [%2];"
                 : "=r"(r[0]), "=r"(r[1]) : "r"(a));
}
__device__ __forceinline__ void mma16816(float* d, const uint32_t* a,
                                         const uint32_t* b) {
    asm volatile("mma.sync.aligned.m16n8k16.row.col.f32.bf16.bf16.f32 "
                 "{%0,%1,%2,%3}, {%4,%5,%6,%7}, {%8,%9}, {%0,%1,%2,%3};"
                 : "+f"(d[0]), "+f"(d[1]), "+f"(d[2]), "+f"(d[3])
                 : "r"(a[0]), "r"(a[1]), "r"(a[2]), "r"(a[3]),
                   "r"(b[0]), "r"(b[1]));
}

// fp32 x8 -> bf16 hi (16B) + bf16 lo (16B)
__device__ __forceinline__ void split8(float4 v0, float4 v1,
                                       uint4& hi, uint4& lo) {
    float f[8] = {v0.x, v0.y, v0.z, v0.w, v1.x, v1.y, v1.z, v1.w};
    uint32_t h[4], l[4];
#pragma unroll
    for (int i = 0; i < 4; i++) {
        __nv_bfloat16 h0 = __float2bfloat16(f[2 * i]);
        __nv_bfloat16 h1 = __float2bfloat16(f[2 * i + 1]);
        __nv_bfloat16 l0 = __float2bfloat16(f[2 * i]     - __bfloat162float(h0));
        __nv_bfloat16 l1 = __float2bfloat16(f[2 * i + 1] - __bfloat162float(h1));
        h[i] = (uint32_t)__bfloat16_as_ushort(h0) |
               ((uint32_t)__bfloat16_as_ushort(h1) << 16);
        l[i] = (uint32_t)__bfloat16_as_ushort(l0) |
               ((uint32_t)__bfloat16_as_ushort(l1) << 16);
    }
    hi = make_uint4(h[0], h[1], h[2], h[3]);
    lo = make_uint4(l[0], l[1], l[2], l[3]);
}

// ======================= mma.sync GEMM ======================================
// C[M,N] = A[M,K] @ W[N,K]^T (+bias)(+gelu)(+res), bf16x3 split, fp32 accum.
// CTA 128x128 tile, 256 threads (8 warps of 64x32), K staged in 64-chunks.
// SMEM layout per chunk: [128 rows][64 k] bf16, 128B/row, 16B groups XOR-swizzled.
#define GO_BIAS 0u
#define GO_AH   1024u
#define GO_AL   (1024u + 16384u)
#define GO_WH   (1024u + 32768u)
#define GO_WL   (1024u + 49152u)
#define G_SMEM  (1024 + 4 * 16384)   // 66560

template<bool GELU, bool RES, bool HASB>
__global__ __launch_bounds__(256)
void mgemm_kernel(const float* __restrict__ A, const float* __restrict__ W,
                  const float* __restrict__ bias, const float* __restrict__ res,
                  float* __restrict__ C, int M, int N, int K)
{
    char* smem = dyn_smem;
    const uint32_t sb = smem_u32(smem);
    const int tid  = threadIdx.x;
    const int lane = tid & 31;
    const int warp = tid >> 5;
    const int bm = blockIdx.y << 7;
    const int bn = blockIdx.x << 7;
    const int wm = (warp >> 2) << 6;     // 0 / 64
    const int wn = (warp & 3) << 5;      // 0/32/64/96

    float* sbias = (float*)(smem + GO_BIAS);
    if (HASB && tid < 128) sbias[tid] = bias[bn + tid];

    float acc[4][4][4];
#pragma unroll
    for (int i = 0; i < 4; i++)
#pragma unroll
        for (int j = 0; j < 4; j++)
#pragma unroll
            for (int k = 0; k < 4; k++) acc[i][j][k] = 0.0f;

    // per-lane ldmatrix row/colgroup selectors
    const int a_row = lane & 15;          // row within 16-row tile
    const int a_cg  = lane >> 4;          // 0/1 -> k0 / k0+8
    const int b_row = lane & 7;           // n within 8
    const int b_cg  = (lane >> 3) & 1;    // k0 / k0+8 (lanes 0..15 used)

    const int g2s_row = tid >> 3;         // 0..31 step rows (it adds 32)
    const int g2s_g   = tid & 7;          // 16B k-group 0..7

    for (int kc = 0; kc < K; kc += 64) {
        __syncthreads();
        // ---- global -> smem, fp32 -> bf16 hi/lo, swizzled ----
#pragma unroll
        for (int it = 0; it < 4; it++) {
            int row = g2s_row + it * 32;
            int g   = g2s_g;
            uint32_t off = (uint32_t)(row * 128 + ((g ^ (row & 7)) << 4));
            const float* pa = A + (size_t)(bm + row) * K + kc + g * 8;
            float4 a0 = *(const float4*)(pa);
            float4 a1 = *(const float4*)(pa + 4);
            uint4 hi, lo; split8(a0, a1, hi, lo);
            *(uint4*)(smem + GO_AH + off) = hi;
            *(uint4*)(smem + GO_AL + off) = lo;
            const float* pw = W + (size_t)(bn + row) * K + kc + g * 8;
            float4 w0 = *(const float4*)(pw);
            float4 w1 = *(const float4*)(pw + 4);
            split8(w0, w1, hi, lo);
            *(uint4*)(smem + GO_WH + off) = hi;
            *(uint4*)(smem + GO_WL + off) = lo;
        }
        __syncthreads();

        // ---- 4 k-steps of 16 ----
#pragma unroll
        for (int ks = 0; ks < 4; ks++) {
            uint32_t ah[4][4], wh[4][2];
#pragma unroll
            for (int mt = 0; mt < 4; mt++) {
                int row = wm + mt * 16 + a_row;
                int cg  = ks * 2 + a_cg;
                ldsm4(sb + GO_AH + row * 128 + ((cg ^ (row & 7)) << 4), ah[mt]);
            }
#pragma unroll
            for (int nt = 0; nt < 4; nt++) {
                int row = wn + nt * 8 + b_row;
                int cg  = ks * 2 + b_cg;
                ldsm2(sb + GO_WH + row * 128 + ((cg ^ (row & 7)) << 4), wh[nt]);
            }
#pragma unroll
            for (int mt = 0; mt < 4; mt++)
#pragma unroll
                for (int nt = 0; nt < 4; nt++)
                    mma16816(acc[mt][nt], ah[mt], wh[nt]);

            // pass 2: Al * Wh
#pragma unroll
            for (int mt = 0; mt < 4; mt++) {
                uint32_t al[4];
                int row = wm + mt * 16 + a_row;
                int cg  = ks * 2 + a_cg;
                ldsm4(sb + GO_AL + row * 128 + ((cg ^ (row & 7)) << 4), al);
#pragma unroll
                for (int nt = 0; nt < 4; nt++)
                    mma16816(acc[mt][nt], al, wh[nt]);
            }
            // pass 3: Ah * Wl
#pragma unroll
            for (int nt = 0; nt < 4; nt++) {
                uint32_t wl[2];
                int row = wn + nt * 8 + b_row;
                int cg  = ks * 2 + b_cg;
                ldsm2(sb + GO_WL + row * 128 + ((cg ^ (row & 7)) << 4), wl);
#pragma unroll
                for (int mt = 0; mt < 4; mt++)
                    mma16816(acc[mt][nt], ah[mt], wl);
            }
        }
    }

    // ---- epilogue: registers -> global ----
#pragma unroll
    for (int mt = 0; mt < 4; mt++) {
        int r = bm + wm + mt * 16 + (lane >> 2);
#pragma unroll
        for (int nt = 0; nt < 4; nt++) {
            int cl = wn + nt * 8 + ((lane & 3) << 1);
            int c  = bn + cl;
            float2 v0 = make_float2(acc[mt][nt][0], acc[mt][nt][1]);
            float2 v1 = make_float2(acc[mt][nt][2], acc[mt][nt][3]);
            if (HASB) {
                float b0 = sbias[cl], b1 = sbias[cl + 1];
                v0.x += b0; v0.y += b1; v1.x += b0; v1.y += b1;
            }
            if (GELU) {
                v0.x = 0.5f * v0.x * (1.0f + erff(v0.x * 0.70710678f));
                v0.y = 0.5f * v0.y * (1.0f + erff(v0.y * 0.70710678f));
                v1.x = 0.5f * v1.x * (1.0f + erff(v1.x * 0.70710678f));
                v1.y = 0.5f * v1.y * (1.0f + erff(v1.y * 0.70710678f));
            }
            size_t i0 = (size_t)r * N + c;
            size_t i1 = (size_t)(r + 8) * N + c;
            if (RES) {
                float2 r0 = *(const float2*)(res + i0);
                float2 r1 = *(const float2*)(res + i1);
                v0.x += r0.x; v0.y += r0.y; v1.x += r1.x; v1.y += r1.y;
            }
            *(float2*)(C + i0) = v0;
            *(float2*)(C + i1) = v1;
        }
    }
}

// ---------------- embedding + positional encoding ---------------------------
__global__ __launch_bounds__(256) void embed_kernel(
    const int* __restrict__ x, const float* __restrict__ ew,
    float* __restrict__ h)
{
    int row = blockIdx.x;
    int d   = threadIdx.x;
    int s   = row & (S_ - 1);
    int tok = x[row];
    int p   = d >> 1;
    float dim_t = powf(10000.0f, (float)p * (1.0f / 128.0f));
    float pos   = (float)s / dim_t;
    float pe    = (d & 1) ? cosf(pos) : sinf(pos);
    h[(size_t)row * D_ + d] = ew[(size_t)tok * D_ + d] + pe;
}

// ---------------- LayerNorm: one warp per 256-elem row ----------------------
__global__ __launch_bounds__(256) void ln_kernel(
    const float* __restrict__ in, float* __restrict__ out,
    const float* __restrict__ w, const float* __restrict__ b)
{
    int warp = threadIdx.x >> 5, lane = threadIdx.x & 31;
    size_t row = (size_t)blockIdx.x * 8 + warp;
    const float* p = in + row * D_;
    float4 a0 = *(const float4*)(p + lane * 4);
    float4 a1 = *(const float4*)(p + 128 + lane * 4);
    float s = a0.x + a0.y + a0.z + a0.w + a1.x + a1.y + a1.z + a1.w;
    float q = a0.x*a0.x + a0.y*a0.y + a0.z*a0.z + a0.w*a0.w
            + a1.x*a1.x + a1.y*a1.y + a1.z*a1.z + a1.w*a1.w;
#pragma unroll
    for (int o = 16; o > 0; o >>= 1) {
        s += __shfl_xor_sync(0xffffffffu, s, o);
        q += __shfl_xor_sync(0xffffffffu, q, o);
    }
    float mean = s * (1.0f / 256.0f);
    float var  = q * (1.0f / 256.0f) - mean * mean;
    float rstd = rsqrtf(var + 1e-5f);
    float4 w0 = *(const float4*)(w + lane * 4);
    float4 w1 = *(const float4*)(w + 128 + lane * 4);
    float4 b0 = *(const float4*)(b + lane * 4);
    float4 b1 = *(const float4*)(b + 128 + lane * 4);
    float4 o0, o1;
    o0.x = (a0.x - mean) * rstd * w0.x + b0.x;
    o0.y = (a0.y - mean) * rstd * w0.y + b0.y;
    o0.z = (a0.z - mean) * rstd * w0.z + b0.z;
    o0.w = (a0.w - mean) * rstd * w0.w + b0.w;
    o1.x = (a1.x - mean) * rstd * w1.x + b1.x;
    o1.y = (a1.y - mean) * rstd * w1.y + b1.y;
    o1.z = (a1.z - mean) * rstd * w1.z + b1.z;
    o1.w = (a1.w - mean) * rstd * w1.w + b1.w;
    float* po = out + row * D_;
    *(float4*)(po + lane * 4)       = o0;
    *(float4*)(po + 128 + lane * 4) = o1;
}

// ---------------- attention: flash-style online softmax ---------------------
#define ATTN_SMEM ((2 * 128 * 64 + 128) * 4)   // 66048

__global__ __launch_bounds__(128) void attn_kernel(
    const float* __restrict__ qkv, const float* __restrict__ ids,
    float* __restrict__ out)
{
    float* sm = (float*)dyn_smem;
    float* Ks  = sm;
    float* Vs  = sm + 128 * 64;
    float* msk = sm + 2 * 128 * 64;
    int h = blockIdx.x, b = blockIdx.y, t = threadIdx.x;
    const float* base = qkv + (size_t)b * S_ * (3 * D_);
    const int qoff = h * DH_;
    const int koff = D_ + h * DH_;
    const int voff = 2 * D_ + h * DH_;

    for (int idx = t; idx < 128 * 16; idx += 128) {
        int r = idx >> 4, c = (idx & 15) << 2;
        *(float4*)(Ks + r * 64 + c) = *(const float4*)(base + (size_t)r * 768 + koff + c);
        *(float4*)(Vs + r * 64 + c) = *(const float4*)(base + (size_t)r * 768 + voff + c);
    }
    msk[t] = ids[b * S_ + t] * -1e9f;

    float q[64];
    {
        const float* qp = base + (size_t)t * 768 + qoff;
#pragma unroll
        for (int i = 0; i < 16; i++) {
            float4 v = *(const float4*)(qp + i * 4);
            q[i*4] = v.x; q[i*4+1] = v.y; q[i*4+2] = v.z; q[i*4+3] = v.w;
        }
    }
    __syncthreads();

    float m = -1e30f, l = 0.0f;
    float o[64];
#pragma unroll
    for (int i = 0; i < 64; i++) o[i] = 0.0f;

    for (int j0 = 0; j0 < 128; j0 += 16) {
        float s[16];
        float cm = -1e30f;
#pragma unroll
        for (int jj = 0; jj < 16; jj++) {
            const float* kr = Ks + (j0 + jj) * 64;
            float dot = 0.0f;
#pragma unroll
            for (int i = 0; i < 16; i++) {
                float4 kv = *(const float4*)(kr + i * 4);
                dot = fmaf(q[i*4],   kv.x, dot);
                dot = fmaf(q[i*4+1], kv.y, dot);
                dot = fmaf(q[i*4+2], kv.z, dot);
                dot = fmaf(q[i*4+3], kv.w, dot);
            }
            float sc = (dot + msk[j0 + jj]) * SCALE_;
            s[jj] = sc;
            cm = fmaxf(cm, sc);
        }
        float mn = fmaxf(m, cm);
        float corr = __expf(m - mn);
        l *= corr;
#pragma unroll
        for (int i = 0; i < 64; i++) o[i] *= corr;
#pragma unroll
        for (int jj = 0; jj < 16; jj++) {
            float pr = __expf(s[jj] - mn);
            l += pr;
            const float* vr = Vs + (j0 + jj) * 64;
#pragma unroll
            for (int i = 0; i < 16; i++) {
                float4 vv = *(const float4*)(vr + i * 4);
                o[i*4]   = fmaf(pr, vv.x, o[i*4]);
                o[i*4+1] = fmaf(pr, vv.y, o[i*4+1]);
                o[i*4+2] = fmaf(pr, vv.z, o[i*4+2]);
                o[i*4+3] = fmaf(pr, vv.w, o[i*4+3]);
            }
        }
        m = mn;
    }
    float inv = 1.0f / l;
    float* op = out + (size_t)(b * S_ + t) * D_ + h * DH_;
#pragma unroll
    for (int i = 0; i < 16; i++) {
        float4 v = make_float4(o[i*4] * inv, o[i*4+1] * inv,
                               o[i*4+2] * inv, o[i*4+3] * inv);
        *(float4*)(op + i * 4) = v;
    }
}

// ---------------- final logits ---------------------------------------------
__global__ __launch_bounds__(256) void logits_kernel(
    const float* __restrict__ hflat, const float* __restrict__ W,
    const float* __restrict__ bias, float* __restrict__ out)
{
    int b = blockIdx.x, t = threadIdx.x;
    const float4* h4  = (const float4*)(hflat + (size_t)b * 32768);
    const float4* w04 = (const float4*)(W);
    const float4* w14 = (const float4*)(W + 32768);
    float a0 = 0.0f, a1 = 0.0f;
    for (int i = t; i < 8192; i += 256) {
        float4 x = h4[i], u = w04[i], v = w14[i];
        a0 += x.x*u.x + x.y*u.y + x.z*u.z + x.w*u.w;
        a1 += x.x*v.x + x.y*v.y + x.z*v.z + x.w*v.w;
    }
    __shared__ float r0[256], r1[256];
    r0[t] = a0; r1[t] = a1;
    __syncthreads();
    for (int s = 128; s > 0; s >>= 1) {
        if (t < s) { r0[t] += r0[t + s]; r1[t] += r1[t + s]; }
        __syncthreads();
    }
    if (t == 0) {
        out[b * 2 + 0] = r0[0] + bias[0];
        out[b * 2 + 1] = r1[0] + bias[1];
    }
}

// ---------------- launch ----------------------------------------------------
extern "C" void kernel_launch(void* const* d_in, const int* in_sizes, int n_in,
                              void* d_out, int out_size)
{
    const int*   x    = (const int*)  d_in[0];
    const float* ids  = (const float*)d_in[1];
    const float* ew   = (const float*)d_in[2];
    const float* n1w  = (const float*)d_in[3];
    const float* n1b  = (const float*)d_in[4];
    const float* piw  = (const float*)d_in[5];
    const float* pow_ = (const float*)d_in[6];
    const float* pob  = (const float*)d_in[7];
    const float* n2w  = (const float*)d_in[8];
    const float* n2b  = (const float*)d_in[9];
    const float* l1w  = (const float*)d_in[10];
    const float* l1b  = (const float*)d_in[11];
    const float* l2w  = (const float*)d_in[12];
    const float* l2b  = (const float*)d_in[13];
    const float* lw   = (const float*)d_in[14];
    const float* lb   = (const float*)d_in[15];
    float* out = (float*)d_out;

    float *h, *hn, *qkvb, *tmp;
    cudaGetSymbolAddress((void**)&h,    g_h);
    cudaGetSymbolAddress((void**)&hn,   g_hn);
    cudaGetSymbolAddress((void**)&qkvb, g_qkv);
    cudaGetSymbolAddress((void**)&tmp,  g_tmp);

    cudaFuncSetAttribute(attn_kernel,
                         cudaFuncAttributeMaxDynamicSharedMemorySize, ATTN_SMEM);
    cudaFuncSetAttribute(mgemm_kernel<false,false,false>,
                         cudaFuncAttributeMaxDynamicSharedMemorySize, G_SMEM);
    cudaFuncSetAttribute(mgemm_kernel<false,true,true>,
                         cudaFuncAttributeMaxDynamicSharedMemorySize, G_SMEM);
    cudaFuncSetAttribute(mgemm_kernel<true,false,true>,
                         cudaFuncAttributeMaxDynamicSharedMemorySize, G_SMEM);

    embed_kernel<<<ROWS_, 256>>>(x, ew, h);

    for (int l = 0; l < L_; l++) {
        ln_kernel<<<ROWS_ / 8, 256>>>(h, hn, n1w + l * D_, n1b + l * D_);
        mgemm_kernel<false,false,false><<<dim3(6, 512), 256, G_SMEM>>>(
            hn, piw + (size_t)l * 3 * D_ * D_, nullptr, nullptr,
            qkvb, ROWS_, 3 * D_, D_);
        attn_kernel<<<dim3(H_, B_), 128, ATTN_SMEM>>>(qkvb, ids, tmp);
        mgemm_kernel<false,true,true><<<dim3(2, 512), 256, G_SMEM>>>(
            tmp, pow_ + (size_t)l * D_ * D_, pob + l * D_, hn,
            h, ROWS_, D_, D_);
        ln_kernel<<<ROWS_ / 8, 256>>>(h, hn, n2w + l * D_, n2b + l * D_);
        mgemm_kernel<true,false,true><<<dim3(3, 512), 256, G_SMEM>>>(
            hn, l1w + (size_t)l * FF_ * D_, l1b + l * FF_, nullptr,
            tmp, ROWS_, FF_, D_);
        mgemm_kernel<false,true,true><<<dim3(2, 512), 256, G_SMEM>>>(
            tmp, l2w + (size_t)l * D_ * FF_, l2b + l * D_, hn,
            h, ROWS_, D_, FF_);
    }

    logits_kernel<<<B_, 256>>>(h, lw, lb, out);
}